// round 15
// baseline (speedup 1.0000x reference)
#include <cuda_runtime.h>
#include <cuda_bf16.h>

#define IMG_W 512
#define IMG_H 512
#define SUBROWS 32          // rows per block strip
#define NTHREADS 128        // 4 warps; warp w owns cols [w*128, w*128+128)

// Zero row for out-of-image / past-strip rows: static storage -> zero
// initialized, never written; L2-resident. zbase = g_zrow+4 so
// [col-1, col+4] stays in-bounds for col in [0,508].
__device__ __align__(16) float g_zrow[520];

// 3x3 local variance, stride 1, zero pad 1, divisor 9.
// Warp-autonomous, 4 cols/lane (fully coalesced LDG.128), branch-free row
// loads with a one-row register prefetch. Minimal register footprint ->
// 10 CTAs/SM (40 warps) to probe whether concurrency or the DRAM R/W-mix
// ceiling is binding. Rolling state: vp (prev row), p (2-row sum),
// q (2-row sq-sum). Vertical 3-sum then horizontal 3-tap via shuffles;
// warp-boundary column via scalar rolling state in lanes 0/31.
__global__ __launch_bounds__(NTHREADS, 10)
void ChannelwiseVariance_85091892068508_kernel(const float* __restrict__ x,
                                               float* __restrict__ out)
{
    const int tid  = threadIdx.x;
    const int lane = tid & 31;
    const int w    = tid >> 5;
    const int col  = w * 128 + lane * 4;           // first of 4 owned columns
    const int y0   = blockIdx.x * SUBROWS;         // strip's first output row
    const int rlast = y0 + SUBROWS;                // last input row needed
    const size_t plane = (size_t)blockIdx.y * (size_t)(IMG_H * IMG_W);

    const float* const zbase = g_zrow + 4;
    const bool lane_l = (lane == 0)  && (col != 0);
    const bool lane_r = (lane == 31) && (col + 4 != IMG_W);
    const float inv9 = 1.0f / 9.0f;
    const unsigned fm = 0xffffffffu;

    float vp[4], p[4], q[4];
    #pragma unroll
    for (int j = 0; j < 4; ++j) { vp[j] = 0.f; p[j] = 0.f; q[j] = 0.f; }
    float lxp = 0.f, lp = 0.f, lq = 0.f;           // boundary rolling state
    float rxp = 0.f, rp = 0.f, rq = 0.f;           // (lanes 0 / 31)

    // Branch-free row-pointer select.
    auto rowptr = [&](int rn) -> const float* {
        const bool fetch = (rn >= 0) && (rn < IMG_H) && (rn <= rlast);
        return fetch ? (x + plane + (size_t)rn * IMG_W) : zbase;
    };

    // Prologue: prefetch row y0-1.
    const float* rp0 = rowptr(y0 - 1);
    float4 n1 = *reinterpret_cast<const float4*>(rp0 + col);
    float  nl1 = lane_l ? rp0[col - 1] : 0.0f;
    float  nr1 = lane_r ? rp0[col + 4] : 0.0f;

    #pragma unroll 2
    for (int it = 0; it < SUBROWS + 2; ++it) {
        const int r = y0 - 1 + it;

        // Consume prefetched row r.
        const float4 v = n1;
        const float lxn = nl1, rxn = nr1;

        // Prefetch row r+1.
        const float* prp = rowptr(r + 1);
        n1  = *reinterpret_cast<const float4*>(prp + col);
        nl1 = lane_l ? prp[col - 1] : 0.0f;
        nr1 = lane_r ? prp[col + 4] : 0.0f;

        float vc[4] = {v.x, v.y, v.z, v.w};

        // Vertical 3-sums for output row r-1, roll state forward.
        float S1[4], S2[4];
        #pragma unroll
        for (int j = 0; j < 4; ++j) {
            const float sq = vc[j] * vc[j];
            S1[j] = p[j] + vc[j];
            S2[j] = q[j] + sq;
            p[j]  = vp[j] + vc[j];
            q[j]  = fmaf(vp[j], vp[j], sq);
            vp[j] = vc[j];
        }
        // Boundary scalars (live in lanes 0 / 31).
        const float lsq = lxn * lxn, rsq = rxn * rxn;
        const float lS1 = lp + lxn, lS2 = lq + lsq;
        const float rS1 = rp + rxn, rS2 = rq + rsq;
        lp = lxp + lxn; lq = fmaf(lxp, lxp, lsq); lxp = lxn;
        rp = rxp + rxn; rq = fmaf(rxp, rxp, rsq); rxp = rxn;

        if (it >= 2) {
            // Horizontal halo of vertical sums via shuffles.
            float sv_l = __shfl_up_sync(fm, S1[3], 1);
            float sq_l = __shfl_up_sync(fm, S2[3], 1);
            float sv_r = __shfl_down_sync(fm, S1[0], 1);
            float sq_r = __shfl_down_sync(fm, S2[0], 1);
            if (lane == 0)  { sv_l = lS1; sq_l = lS2; }
            if (lane == 31) { sv_r = rS1; sq_r = rS2; }

            float o[4];
            {
                const float t1 = sv_l + S1[0] + S1[1];
                const float t2 = sq_l + S2[0] + S2[1];
                const float m = t1 * inv9; o[0] = fmaf(-m, m, t2 * inv9);
            }
            {
                const float t1 = S1[0] + S1[1] + S1[2];
                const float t2 = S2[0] + S2[1] + S2[2];
                const float m = t1 * inv9; o[1] = fmaf(-m, m, t2 * inv9);
            }
            {
                const float t1 = S1[1] + S1[2] + S1[3];
                const float t2 = S2[1] + S2[2] + S2[3];
                const float m = t1 * inv9; o[2] = fmaf(-m, m, t2 * inv9);
            }
            {
                const float t1 = S1[2] + S1[3] + sv_r;
                const float t2 = S2[2] + S2[3] + sq_r;
                const float m = t1 * inv9; o[3] = fmaf(-m, m, t2 * inv9);
            }

            const int y = r - 1;
            __stcs(reinterpret_cast<float4*>(out + plane + (size_t)y * IMG_W + col),
                   make_float4(o[0], o[1], o[2], o[3]));
        }
    }
}

extern "C" void kernel_launch(void* const* d_in, const int* in_sizes, int n_in,
                              void* d_out, int out_size)
{
    const float* x = (const float*)d_in[0];
    float* out = (float*)d_out;

    const int planes = in_sizes[0] / (IMG_H * IMG_W);   // 8*32 = 256
    dim3 grid(IMG_H / SUBROWS, planes);                 // (16, 256) = 4096 blocks
    dim3 block(NTHREADS);
    ChannelwiseVariance_85091892068508_kernel<<<grid, block>>>(x, out);
}

// round 16
// speedup vs baseline: 1.0213x; 1.0213x over previous
#include <cuda_runtime.h>
#include <cuda_bf16.h>

#define IMG_W 512
#define IMG_H 512
#define SUBROWS 32          // rows per block strip
#define NTHREADS 128        // 4 warps; warp w owns cols [w*128, w*128+128)

// Zero row for out-of-image / past-strip rows: static storage -> zero
// initialized, never written; L2-resident. zbase = g_zrow+4 so
// [col-1, col+4] stays in-bounds for col in [0,508].
__device__ __align__(16) float g_zrow[520];

// 3x3 local variance, stride 1, zero pad 1, divisor 9.
// Warp-autonomous, 4 cols/lane (fully coalesced LDG.128), branch-free row
// loads with a TWO-row register prefetch pipeline. 56 regs -> 9 CTAs/SM.
// Empirically the best operating point: saturates the ~6.0 TB/s mixed
// R/W memory-system ceiling (75.6% of spec) with minimal traffic (~500 MB).
// Rolling state: vp (prev row), p (2-row sum), q (2-row sq-sum). Vertical
// 3-sum then horizontal 3-tap via shuffles; warp-boundary column via scalar
// rolling state in lanes 0/31.
__global__ __launch_bounds__(NTHREADS, 9)
void ChannelwiseVariance_85091892068508_kernel(const float* __restrict__ x,
                                               float* __restrict__ out)
{
    const int tid  = threadIdx.x;
    const int lane = tid & 31;
    const int w    = tid >> 5;
    const int col  = w * 128 + lane * 4;           // first of 4 owned columns
    const int y0   = blockIdx.x * SUBROWS;         // strip's first output row
    const int rlast = y0 + SUBROWS;                // last input row needed
    const size_t plane = (size_t)blockIdx.y * (size_t)(IMG_H * IMG_W);

    const float* const zbase = g_zrow + 4;
    const bool lane_l = (lane == 0)  && (col != 0);
    const bool lane_r = (lane == 31) && (col + 4 != IMG_W);
    const float inv9 = 1.0f / 9.0f;
    const unsigned fm = 0xffffffffu;

    float vp[4], p[4], q[4];
    #pragma unroll
    for (int j = 0; j < 4; ++j) { vp[j] = 0.f; p[j] = 0.f; q[j] = 0.f; }
    float lxp = 0.f, lp = 0.f, lq = 0.f;           // boundary rolling state
    float rxp = 0.f, rp = 0.f, rq = 0.f;           // (lanes 0 / 31)

    // Branch-free row-pointer select.
    auto rowptr = [&](int rn) -> const float* {
        const bool fetch = (rn >= 0) && (rn < IMG_H) && (rn <= rlast);
        return fetch ? (x + plane + (size_t)rn * IMG_W) : zbase;
    };

    // Prologue: two prefetch stages (rows y0-1 and y0).
    const float* rp0 = rowptr(y0 - 1);
    float4 n1 = *reinterpret_cast<const float4*>(rp0 + col);
    float  nl1 = lane_l ? rp0[col - 1] : 0.0f;
    float  nr1 = lane_r ? rp0[col + 4] : 0.0f;

    const float* rp1 = rowptr(y0);
    float4 n2 = *reinterpret_cast<const float4*>(rp1 + col);
    float  nl2 = lane_l ? rp1[col - 1] : 0.0f;
    float  nr2 = lane_r ? rp1[col + 4] : 0.0f;

    #pragma unroll 2
    for (int it = 0; it < SUBROWS + 2; ++it) {
        const int r = y0 - 1 + it;

        // Consume stage-1 (row r); shift stage-2 -> stage-1.
        const float4 v = n1;
        const float lxn = nl1, rxn = nr1;
        n1 = n2; nl1 = nl2; nr1 = nr2;

        // Issue stage-2 prefetch for row r+2.
        const float* prp = rowptr(r + 2);
        n2  = *reinterpret_cast<const float4*>(prp + col);
        nl2 = lane_l ? prp[col - 1] : 0.0f;
        nr2 = lane_r ? prp[col + 4] : 0.0f;

        float vc[4] = {v.x, v.y, v.z, v.w};

        // Vertical 3-sums for output row r-1, roll state forward.
        float S1[4], S2[4];
        #pragma unroll
        for (int j = 0; j < 4; ++j) {
            const float sq = vc[j] * vc[j];
            S1[j] = p[j] + vc[j];
            S2[j] = q[j] + sq;
            p[j]  = vp[j] + vc[j];
            q[j]  = fmaf(vp[j], vp[j], sq);
            vp[j] = vc[j];
        }
        // Boundary scalars (live in lanes 0 / 31).
        const float lsq = lxn * lxn, rsq = rxn * rxn;
        const float lS1 = lp + lxn, lS2 = lq + lsq;
        const float rS1 = rp + rxn, rS2 = rq + rsq;
        lp = lxp + lxn; lq = fmaf(lxp, lxp, lsq); lxp = lxn;
        rp = rxp + rxn; rq = fmaf(rxp, rxp, rsq); rxp = rxn;

        if (it >= 2) {
            // Horizontal halo of vertical sums via shuffles.
            float sv_l = __shfl_up_sync(fm, S1[3], 1);
            float sq_l = __shfl_up_sync(fm, S2[3], 1);
            float sv_r = __shfl_down_sync(fm, S1[0], 1);
            float sq_r = __shfl_down_sync(fm, S2[0], 1);
            if (lane == 0)  { sv_l = lS1; sq_l = lS2; }
            if (lane == 31) { sv_r = rS1; sq_r = rS2; }

            float o[4];
            {
                const float t1 = sv_l + S1[0] + S1[1];
                const float t2 = sq_l + S2[0] + S2[1];
                const float m = t1 * inv9; o[0] = fmaf(-m, m, t2 * inv9);
            }
            {
                const float t1 = S1[0] + S1[1] + S1[2];
                const float t2 = S2[0] + S2[1] + S2[2];
                const float m = t1 * inv9; o[1] = fmaf(-m, m, t2 * inv9);
            }
            {
                const float t1 = S1[1] + S1[2] + S1[3];
                const float t2 = S2[1] + S2[2] + S2[3];
                const float m = t1 * inv9; o[2] = fmaf(-m, m, t2 * inv9);
            }
            {
                const float t1 = S1[2] + S1[3] + sv_r;
                const float t2 = S2[2] + S2[3] + sq_r;
                const float m = t1 * inv9; o[3] = fmaf(-m, m, t2 * inv9);
            }

            const int y = r - 1;
            __stcs(reinterpret_cast<float4*>(out + plane + (size_t)y * IMG_W + col),
                   make_float4(o[0], o[1], o[2], o[3]));
        }
    }
}

extern "C" void kernel_launch(void* const* d_in, const int* in_sizes, int n_in,
                              void* d_out, int out_size)
{
    const float* x = (const float*)d_in[0];
    float* out = (float*)d_out;

    const int planes = in_sizes[0] / (IMG_H * IMG_W);   // 8*32 = 256
    dim3 grid(IMG_H / SUBROWS, planes);                 // (16, 256) = 4096 blocks
    dim3 block(NTHREADS);
    ChannelwiseVariance_85091892068508_kernel<<<grid, block>>>(x, out);
}